// round 8
// baseline (speedup 1.0000x reference)
#include <cuda_runtime.h>
#include <math.h>

#define BATCH 8
#define SEQ 1024
#define DIM 512
#define HEADS 8
#define HDIM 64
#define VOCAB 1024
#define M_ROWS (BATCH*SEQ)          /* 8192 */
#define MTOT (M_ROWS*DIM)           /* 4,194,304 floats */
#define EPSF 1e-5f

// ---------------- scratch (device globals; no allocation allowed) ----------------
__device__ float g_x[MTOT];   // 0: x (post embed-LN), later LN(x2)
__device__ float g_q[MTOT];   // 1: q proj, later FFN hidden
__device__ float g_k[MTOT];   // 2: k proj, later final LN output
__device__ float g_v[MTOT];   // 3: v proj, later x4
__device__ float g_g[MTOT];   // 4: gate proj, later gated value z
__device__ float g_y[MTOT];   // 5: retention output (group-normed)
__device__ float g_t[MTOT];   // 6: x2 = z@Wo + x (residual carrier)

__device__ __forceinline__ float* buf(int s) {
    switch (s) {
        case 0: return g_x;
        case 1: return g_q;
        case 2: return g_k;
        case 3: return g_v;
        case 4: return g_g;
        case 5: return g_y;
        default: return g_t;
    }
}

// ---------------- embed + layernorm (warp per row) ----------------
__global__ void embed_ln_kernel(const int* __restrict__ ids,
                                const float* __restrict__ tables,
                                const float* __restrict__ pos,
                                const float* __restrict__ gam,
                                const float* __restrict__ bet) {
    int warp = (blockIdx.x * blockDim.x + threadIdx.x) >> 5;
    if (warp >= M_ROWS) return;
    int lane = threadIdx.x & 31;
    int s = warp & (SEQ - 1);
    int id = ids[2 * BATCH * SEQ + warp];
    const float4* t4 = (const float4*)(tables + (size_t)(2 * VOCAB + id) * DIM);
    const float4* p4 = (const float4*)(pos + (size_t)(2 * SEQ + s) * DIM);
    float4 v[4];
    float s1 = 0.f, s2 = 0.f;
#pragma unroll
    for (int k = 0; k < 4; k++) {
        int c4 = lane + k * 32;
        float4 a = t4[c4], b = p4[c4];
        v[k] = make_float4(a.x + b.x, a.y + b.y, a.z + b.z, a.w + b.w);
        s1 += v[k].x + v[k].y + v[k].z + v[k].w;
        s2 += v[k].x * v[k].x + v[k].y * v[k].y + v[k].z * v[k].z + v[k].w * v[k].w;
    }
#pragma unroll
    for (int o = 16; o; o >>= 1) {
        s1 += __shfl_xor_sync(0xffffffffu, s1, o);
        s2 += __shfl_xor_sync(0xffffffffu, s2, o);
    }
    float mean = s1 * (1.f / DIM);
    float var = s2 * (1.f / DIM) - mean * mean;
    float r = rsqrtf(var + EPSF);
    float4* out4 = (float4*)(g_x + (size_t)warp * DIM);
#pragma unroll
    for (int k = 0; k < 4; k++) {
        int c4 = lane + k * 32;
        float4 gm = ((const float4*)gam)[c4];
        float4 bt = ((const float4*)bet)[c4];
        float4 o;
        o.x = (v[k].x - mean) * r * gm.x + bt.x;
        o.y = (v[k].y - mean) * r * gm.y + bt.y;
        o.z = (v[k].z - mean) * r * gm.z + bt.z;
        o.w = (v[k].w - mean) * r * gm.w + bt.w;
        out4[c4] = o;
    }
}

// ---------------- plain layernorm (warp per row), selector-based ----------------
__global__ void ln_kernel(int in_sel, int out_sel,
                          const float* __restrict__ gam,
                          const float* __restrict__ bet) {
    int warp = (blockIdx.x * blockDim.x + threadIdx.x) >> 5;
    if (warp >= M_ROWS) return;
    int lane = threadIdx.x & 31;
    const float* in = buf(in_sel);
    float* out = buf(out_sel);
    const float4* src = (const float4*)(in + (size_t)warp * DIM);
    float4 v[4];
    float s1 = 0.f, s2 = 0.f;
#pragma unroll
    for (int k = 0; k < 4; k++) {
        int c4 = lane + k * 32;
        v[k] = src[c4];
        s1 += v[k].x + v[k].y + v[k].z + v[k].w;
        s2 += v[k].x * v[k].x + v[k].y * v[k].y + v[k].z * v[k].z + v[k].w * v[k].w;
    }
#pragma unroll
    for (int o = 16; o; o >>= 1) {
        s1 += __shfl_xor_sync(0xffffffffu, s1, o);
        s2 += __shfl_xor_sync(0xffffffffu, s2, o);
    }
    float mean = s1 * (1.f / DIM);
    float var = s2 * (1.f / DIM) - mean * mean;
    float r = rsqrtf(var + EPSF);
    float4* out4 = (float4*)(out + (size_t)warp * DIM);
#pragma unroll
    for (int k = 0; k < 4; k++) {
        int c4 = lane + k * 32;
        float4 gm = ((const float4*)gam)[c4];
        float4 bt = ((const float4*)bet)[c4];
        float4 o;
        o.x = (v[k].x - mean) * r * gm.x + bt.x;
        o.y = (v[k].y - mean) * r * gm.y + bt.y;
        o.z = (v[k].z - mean) * r * gm.z + bt.z;
        o.w = (v[k].w - mean) * r * gm.w + bt.w;
        out4[c4] = o;
    }
}

// ---------------- SGEMM: C[M,512] = A[M,512] @ W[512,512] (+bias)(+relu)(+res) ----------------
// flags: bit0 bias, bit1 relu, bit2 residual-add. A/C/res are scratch selectors.
#define GBM 128
#define GBN 128
#define GBK 8
__global__ __launch_bounds__(256) void sgemm_kernel(int a_sel,
                                                    const float* __restrict__ B,
                                                    int c_sel,
                                                    const float* __restrict__ bias,
                                                    int res_sel,
                                                    int flags) {
    __shared__ float As[GBK][GBM];
    __shared__ float Bs[GBK][GBN];
    const float* A = buf(a_sel);
    float* C = buf(c_sel);
    int tid = threadIdx.x;
    int bm = blockIdx.y * GBM;
    int bn = blockIdx.x * GBN;
    int tx = tid & 15, ty = tid >> 4;
    float acc[8][8] = {};
    int arow = tid >> 1, acol = (tid & 1) * 4;
    int brow = tid >> 5, bcol = (tid & 31) * 4;
    const float* Aptr = A + (size_t)(bm + arow) * DIM + acol;
    const float* Bptr = B + (size_t)brow * DIM + bn + bcol;

    float4 a = *(const float4*)(Aptr);
    float4 b = *(const float4*)(Bptr);
    for (int k0 = 0; k0 < DIM; k0 += GBK) {
        As[acol + 0][arow] = a.x;
        As[acol + 1][arow] = a.y;
        As[acol + 2][arow] = a.z;
        As[acol + 3][arow] = a.w;
        *(float4*)&Bs[brow][bcol] = b;
        __syncthreads();
        if (k0 + GBK < DIM) {   // prefetch next tile while computing
            a = *(const float4*)(Aptr + k0 + GBK);
            b = *(const float4*)(Bptr + (size_t)(k0 + GBK) * DIM);
        }
#pragma unroll
        for (int k = 0; k < GBK; k++) {
            float ar[8], br[8];
            *(float4*)(&ar[0]) = *(const float4*)(&As[k][ty * 8]);
            *(float4*)(&ar[4]) = *(const float4*)(&As[k][ty * 8 + 4]);
            *(float4*)(&br[0]) = *(const float4*)(&Bs[k][tx * 8]);
            *(float4*)(&br[4]) = *(const float4*)(&Bs[k][tx * 8 + 4]);
#pragma unroll
            for (int i = 0; i < 8; i++)
#pragma unroll
                for (int j = 0; j < 8; j++) acc[i][j] += ar[i] * br[j];
        }
        __syncthreads();
    }
    bool hb = flags & 1, hr = flags & 2, hres = flags & 4;
    const float* res = hres ? buf(res_sel) : (const float*)0;
    float bvals[8];
#pragma unroll
    for (int j = 0; j < 8; j++) bvals[j] = hb ? bias[bn + tx * 8 + j] : 0.f;
#pragma unroll
    for (int i = 0; i < 8; i++) {
        int row = bm + ty * 8 + i;
        float* crow = C + (size_t)row * DIM + bn + tx * 8;
#pragma unroll
        for (int j = 0; j < 8; j++) {
            float v = acc[i][j] + bvals[j];
            if (hr) v = fmaxf(v, 0.f);
            crow[j] = v;
        }
        if (hres) {
            const float* rrow = res + (size_t)row * DIM + bn + tx * 8;
#pragma unroll
            for (int j = 0; j < 8; j++) crow[j] += rrow[j];
        }
    }
}

// ---------------- fused causal retention + per-head group norm ----------------
// grid (SEQ/64, HEADS, BATCH), 256 threads, STATIC smem (42.5 KB, no opt-in).
// 64-row Q block; 32-row K/V chunks. Strides chosen for aligned vector loads:
//   QsT stride 68 (float4-aligned), KsT stride 34 (float2-aligned), Ss stride 36.
#define QS 68
#define KS 34
#define SS 36
__global__ __launch_bounds__(256) void retention_kernel() {
    __shared__ float QsT[64 * QS];   // [d][n] : QsT[d*68 + n]
    __shared__ float KsT[64 * KS];   // [d][m] : KsT[d*34 + m], m in 0..31
    __shared__ float Vs[32 * 64];    // [m][c] : Vs[m*64 + c]
    __shared__ float Ss[64 * SS];    // [n][m] : Ss[n*36 + m]
    int b = blockIdx.z, h = blockIdx.y;
    int n0 = blockIdx.x * 64;
    int tid = threadIdx.x;
    int tx = tid & 15, ty = tid >> 4;   // stage1: 4n x 2m per thread; stage2: 4n x 4c
    float gamma = 1.f - exp2f(-5.f - (float)h);
    float l2g = log2f(gamma);

    {   // load Q tile (64 rows x 64 d), transposed into QsT
        int row = tid >> 2, cq = tid & 3;
        const float* src = g_q + ((size_t)(b * SEQ + n0 + row)) * DIM + h * HDIM;
#pragma unroll
        for (int rep = 0; rep < 4; rep++) {
            int c = (cq + rep * 4) * 4;
            float4 v = *(const float4*)(src + c);
            QsT[(c + 0) * QS + row] = v.x;
            QsT[(c + 1) * QS + row] = v.y;
            QsT[(c + 2) * QS + row] = v.z;
            QsT[(c + 3) * QS + row] = v.w;
        }
    }

    float acc[4][4] = {};
    for (int m0 = 0; m0 <= n0 + 32; m0 += 32) {
        __syncthreads();  // prior stage2 done with Ss/Vs; Q store visible (1st iter)
        {   // load K (transposed) + V (natural), 32 rows x 64 cols each
            int row = tid >> 3, cq = tid & 7;
            const float* ksrc = g_k + ((size_t)(b * SEQ + m0 + row)) * DIM + h * HDIM;
            const float* vsrc = g_v + ((size_t)(b * SEQ + m0 + row)) * DIM + h * HDIM;
#pragma unroll
            for (int rep = 0; rep < 2; rep++) {
                int c = cq * 8 + rep * 4;
                float4 kv = *(const float4*)(ksrc + c);
                KsT[(c + 0) * KS + row] = kv.x;
                KsT[(c + 1) * KS + row] = kv.y;
                KsT[(c + 2) * KS + row] = kv.z;
                KsT[(c + 3) * KS + row] = kv.w;
                *(float4*)&Vs[row * 64 + c] = *(const float4*)(vsrc + c);
            }
        }
        __syncthreads();
        // stage 1: s[n_local 4][m_local 2] = q . k
        float s[4][2] = {};
#pragma unroll 8
        for (int d = 0; d < 64; d++) {
            float a[4], bb[2];
            *(float4*)a  = *(const float4*)&QsT[d * QS + ty * 4];
            *(float2*)bb = *(const float2*)&KsT[d * KS + tx * 2];
#pragma unroll
            for (int i = 0; i < 4; i++)
#pragma unroll
                for (int j = 0; j < 2; j++) s[i][j] += a[i] * bb[j];
        }
        // scale + causal decay, write to Ss
#pragma unroll
        for (int i = 0; i < 4; i++)
#pragma unroll
            for (int j = 0; j < 2; j++) {
                int diff = (n0 + ty * 4 + i) - (m0 + tx * 2 + j);
                float val = (diff < 0) ? 0.f
                          : s[i][j] * 0.125f * exp2f((float)diff * l2g);
                Ss[(ty * 4 + i) * SS + tx * 2 + j] = val;
            }
        __syncthreads();
        // stage 2: acc[4n][4c] += S V
#pragma unroll 8
        for (int m = 0; m < 32; m++) {
            float a[4], bb[4];
#pragma unroll
            for (int i = 0; i < 4; i++) a[i] = Ss[(ty * 4 + i) * SS + m];
            *(float4*)bb = *(const float4*)&Vs[m * 64 + tx * 4];
#pragma unroll
            for (int i = 0; i < 4; i++)
#pragma unroll
                for (int j = 0; j < 4; j++) acc[i][j] += a[i] * bb[j];
        }
    }

    // per-row group norm over hd=64 (row's 64 channels live on the 16 tx lanes)
#pragma unroll
    for (int i = 0; i < 4; i++) {
        float s1 = acc[i][0] + acc[i][1] + acc[i][2] + acc[i][3];
        float s2 = acc[i][0] * acc[i][0] + acc[i][1] * acc[i][1] +
                   acc[i][2] * acc[i][2] + acc[i][3] * acc[i][3];
#pragma unroll
        for (int o = 8; o; o >>= 1) {
            s1 += __shfl_xor_sync(0xffffffffu, s1, o);
            s2 += __shfl_xor_sync(0xffffffffu, s2, o);
        }
        float mean = s1 * (1.f / 64.f);
        float var = s2 * (1.f / 64.f) - mean * mean;
        float r = rsqrtf(var + EPSF);
        int n = n0 + ty * 4 + i;
        float4 o4;
        o4.x = (acc[i][0] - mean) * r;
        o4.y = (acc[i][1] - mean) * r;
        o4.z = (acc[i][2] - mean) * r;
        o4.w = (acc[i][3] - mean) * r;
        *(float4*)&g_y[((size_t)(b * SEQ + n)) * DIM + h * HDIM + tx * 4] = o4;
    }
}

// ---------------- gate: z = swish(xg) * y (in place into g_g) ----------------
__global__ void gate_kernel() {
    int i = blockIdx.x * blockDim.x + threadIdx.x;
    float4 g = ((const float4*)g_g)[i];
    float4 y = ((const float4*)g_y)[i];
    float4 o;
    o.x = g.x * y.x / (1.f + expf(-g.x));
    o.y = g.y * y.y / (1.f + expf(-g.y));
    o.z = g.z * y.z / (1.f + expf(-g.z));
    o.w = g.w * y.w / (1.f + expf(-g.w));
    ((float4*)g_g)[i] = o;
}

// ---------------- final: out[b] = sigmoid(x5[b].flatten() . fc_W + fc_b) ----------------
__global__ void final_kernel(int in_sel,
                             const float* __restrict__ w,
                             const float* __restrict__ bias,
                             float* __restrict__ out) {
    int b = blockIdx.x;
    const float* x = buf(in_sel);
    const float4* xr = (const float4*)(x + (size_t)b * SEQ * DIM);
    const float4* wr = (const float4*)w;
    float sum = 0.f;
    const int n4 = SEQ * DIM / 4;
    for (int i = threadIdx.x; i < n4; i += blockDim.x) {
        float4 a = xr[i], c = wr[i];
        sum += a.x * c.x + a.y * c.y + a.z * c.z + a.w * c.w;
    }
    __shared__ float red[32];
#pragma unroll
    for (int o = 16; o; o >>= 1) sum += __shfl_xor_sync(0xffffffffu, sum, o);
    if ((threadIdx.x & 31) == 0) red[threadIdx.x >> 5] = sum;
    __syncthreads();
    if (threadIdx.x < 32) {
        float v = (threadIdx.x < (int)(blockDim.x >> 5)) ? red[threadIdx.x] : 0.f;
#pragma unroll
        for (int o = 16; o; o >>= 1) v += __shfl_xor_sync(0xffffffffu, v, o);
        if (threadIdx.x == 0) out[b] = 1.f / (1.f + expf(-(v + bias[0])));
    }
}

// ---------------- launch: kernel launches ONLY (maximally capture-safe) ----------------
extern "C" void kernel_launch(void* const* d_in, const int* in_sizes, int n_in,
                              void* d_out, int out_size) {
    (void)in_sizes; (void)n_in; (void)out_size;
    const int*   ids    = (const int*)d_in[0];
    const float* tables = (const float*)d_in[1];
    const float* pos    = (const float*)d_in[2];
    const float* lng    = (const float*)d_in[3];
    const float* lnb    = (const float*)d_in[4];
    const float* Wq     = (const float*)d_in[5];
    const float* Wk     = (const float*)d_in[6];
    const float* Wv     = (const float*)d_in[7];
    const float* Wg     = (const float*)d_in[8];
    const float* Wo     = (const float*)d_in[9];
    const float* W1     = (const float*)d_in[10];
    const float* b1     = (const float*)d_in[11];
    const float* W2     = (const float*)d_in[12];
    const float* b2     = (const float*)d_in[13];
    const float* fcW    = (const float*)d_in[14];
    const float* fcb    = (const float*)d_in[15];
    float* out = (float*)d_out;

    dim3 ggrid(DIM / GBN, M_ROWS / GBM);  // (4, 64)

    // Only the last vocab pass (i = NVOCAB-1 = 2) survives in the reference.
    embed_ln_kernel<<<M_ROWS / 8, 256>>>(ids, tables, pos, lng, lnb);   // -> g_x(0)
    sgemm_kernel<<<ggrid, 256>>>(0, Wq, 1, nullptr, 0, 0);              // q
    sgemm_kernel<<<ggrid, 256>>>(0, Wk, 2, nullptr, 0, 0);              // k
    sgemm_kernel<<<ggrid, 256>>>(0, Wv, 3, nullptr, 0, 0);              // v
    sgemm_kernel<<<ggrid, 256>>>(0, Wg, 4, nullptr, 0, 0);              // gate proj
    retention_kernel<<<dim3(SEQ / 64, HEADS, BATCH), 256>>>();          // -> g_y(5)
    gate_kernel<<<MTOT / 4 / 256, 256>>>();                             // g_g = z
    sgemm_kernel<<<ggrid, 256>>>(4, Wo, 6, nullptr, 0, 4);              // x2 = z@Wo + x
    ln_kernel<<<M_ROWS / 8, 256>>>(6, 0, lng, lnb);                     // x3 = LN(x2)
    sgemm_kernel<<<ggrid, 256>>>(0, W1, 1, b1, 0, 3);                   // h = relu(x3@W1+b1)
    sgemm_kernel<<<ggrid, 256>>>(1, W2, 3, b2, 6, 5);                   // x4 = h@W2+b2+x2
    ln_kernel<<<M_ROWS / 8, 256>>>(3, 2, lng, lnb);                     // x5 = LN(x4)
    final_kernel<<<BATCH, 1024>>>(2, fcW, fcb, out);
}